// round 1
// baseline (speedup 1.0000x reference)
#include <cuda_runtime.h>
#include <cstdint>

#define N_NODES 8192
#define N_EDGES 32768
#define HID 128
#define N_SUB 512
#define N_GRAPH 32

// ---------------- device scratch (static; no allocations) ----------------
__device__ float g_S[8192 * 64 * 128];     // [n][i][k] i-major per node; row-major [N, K]
__device__ float g_W2t[8192 * 64];         // [K][co]
__device__ float g_xa[N_NODES * 64];
__device__ float g_xb[N_NODES * 64];
__device__ float g_xs[N_NODES * 64];       // sum of x[src] over incoming edges
__device__ float g_agg[N_NODES * 64];      // GEMM output accumulator
__device__ int   g_rowptr[N_NODES + 1];
__device__ int   g_fill[N_NODES];
__device__ int   g_eperm[N_EDGES];
__device__ float g_sub[N_SUB * 64];
__device__ float g_subcnt[N_SUB];
__device__ float g_graph[N_GRAPH * 64];
__device__ float g_graphcnt[N_GRAPH];

// ---------------- small utility kernels ----------------
__global__ void k_zero_rowptr() {
    int i = blockIdx.x * blockDim.x + threadIdx.x;
    if (i <= N_NODES) g_rowptr[i] = 0;
}

__global__ void k_zero_agg(int n) {
    int i = blockIdx.x * blockDim.x + threadIdx.x;
    if (i < n) g_agg[i] = 0.f;
}

__global__ void k_zero_pools() {
    int i = blockIdx.x * blockDim.x + threadIdx.x;
    if (i < N_SUB * 64)   g_sub[i] = 0.f;
    if (i < N_SUB)        g_subcnt[i] = 0.f;
    if (i < N_GRAPH * 64) g_graph[i] = 0.f;
    if (i < N_GRAPH)      g_graphcnt[i] = 0.f;
}

__global__ void k_count(const int* __restrict__ ei) {
    int e = blockIdx.x * blockDim.x + threadIdx.x;
    if (e < N_EDGES) atomicAdd(&g_rowptr[ei[N_EDGES + e] + 1], 1);
}

// single-block scan over 8192 counts -> exclusive rowptr; also init g_fill
__global__ void k_scan() {
    __shared__ int part[1024];
    int t = threadIdx.x;
    int v[8];
    int run = 0;
#pragma unroll
    for (int q = 0; q < 8; q++) { run += g_rowptr[1 + t * 8 + q]; v[q] = run; }
    part[t] = run;
    __syncthreads();
    int sum = run;
    for (int off = 1; off < 1024; off <<= 1) {
        int other = (t >= off) ? part[t - off] : 0;
        __syncthreads();
        sum += other;
        part[t] = sum;
        __syncthreads();
    }
    int add = sum - run;  // exclusive prefix for this thread's chunk
#pragma unroll
    for (int q = 0; q < 8; q++) {
        int val = v[q] + add;
        int pos = 1 + t * 8 + q;
        g_rowptr[pos] = val;
        if (pos < N_NODES) g_fill[pos] = val;
    }
    if (t == 0) { g_rowptr[0] = 0; g_fill[0] = 0; }
}

__global__ void k_fill(const int* __restrict__ ei) {
    int e = blockIdx.x * blockDim.x + threadIdx.x;
    if (e < N_EDGES) {
        int d = ei[N_EDGES + e];
        int pos = atomicAdd(&g_fill[d], 1);
        g_eperm[pos] = e;
    }
}

// W2t[(i*128+k)*co + o] = W2[(k*ci + i)*co + o]
__global__ void k_w2t(const float* __restrict__ W2, int ci, int co, int K) {
    int idx = blockIdx.x * blockDim.x + threadIdx.x;
    if (idx >= K * co) return;
    int kk = idx / co, o = idx % co;
    int i = kk >> 7, k = kk & 127;
    g_W2t[idx] = W2[(k * ci + i) * co + o];
}

// ---------------- scatter: S[n,i,k] = sum_{e->n} h[e,k] * x[src_e, i] ----------------
// One block per node, 128 threads (thread t = hidden channel k). S row held in regs.
template <int CI>
__global__ __launch_bounds__(128) void k_scatter(
    const float* __restrict__ xcur, const int* __restrict__ ei,
    const float* __restrict__ eattr, const float* __restrict__ W1,
    const float* __restrict__ b1)
{
    int n = blockIdx.x;
    int t = threadIdx.x;
    __shared__ float sx[CI];
    __shared__ float sattr[5];

    float w1r[5];
#pragma unroll
    for (int j = 0; j < 5; j++) w1r[j] = W1[j * HID + t];
    float b1r = b1[t];

    float sacc[CI];
#pragma unroll
    for (int i = 0; i < CI; i++) sacc[i] = 0.f;
    float xsacc = 0.f;

    int beg = g_rowptr[n], end = g_rowptr[n + 1];
    for (int j = beg; j < end; j++) {
        int e = g_eperm[j];      // uniform per block -> broadcast loads
        int src = ei[e];
        if (t < 5)  sattr[t] = eattr[e * 5 + t];
        if (t < CI) sx[t] = xcur[src * CI + t];
        __syncthreads();
        float h = b1r;
#pragma unroll
        for (int q = 0; q < 5; q++) h += sattr[q] * w1r[q];
        h = fmaxf(h, 0.f);
#pragma unroll
        for (int i = 0; i < CI; i++) sacc[i] += h * sx[i];
        if (t < CI) xsacc += sx[t];
        __syncthreads();
    }

    size_t base = (size_t)n * CI * HID;
#pragma unroll
    for (int i = 0; i < CI; i++) g_S[base + (size_t)i * HID + t] = sacc[i];
    if (t < CI) g_xs[n * 64 + t] = xsacc;
}

// ---------------- GEMM: g_agg[M, BN] += g_S[M, K] @ g_W2t[K, BN] ----------------
// BM=64, BK=32, 128 threads; thread computes 4 x TN outputs via packed fma.rn.f32x2.
// Split-K across blockIdx.y with atomic accumulation.
template <int BN>
__global__ __launch_bounds__(128) void k_gemm(int K, int kspl)
{
    constexpr int BM = 64, BK = 32;
    constexpr int TN = (BN == 64) ? 8 : 4;
    __shared__ float sA[BK][BM + 1];
    __shared__ float sB[BK][BN];

    const int t   = threadIdx.x;
    const int m0  = blockIdx.x * BM;
    const int k0  = blockIdx.y * kspl;
    const int tym = t >> 3, txn = t & 7;
    const int rm  = tym * 4, rn = txn * TN;

    unsigned long long acc[4][TN / 2];
#pragma unroll
    for (int q = 0; q < 4; q++)
#pragma unroll
        for (int w = 0; w < TN / 2; w++) acc[q][w] = 0ull;

    const int ar = t >> 3;  // 0..15: A row group
    const int ac = t & 7;   // 0..7 : A k group (4 floats)

    for (int kt = k0; kt < k0 + kspl; kt += BK) {
        // load A tile (transposed into sA[k][m])
#pragma unroll
        for (int p = 0; p < 4; p++) {
            int r = ar + 16 * p;
            float4 v = *(const float4*)&g_S[(size_t)(m0 + r) * K + kt + ac * 4];
            sA[ac * 4 + 0][r] = v.x;
            sA[ac * 4 + 1][r] = v.y;
            sA[ac * 4 + 2][r] = v.z;
            sA[ac * 4 + 3][r] = v.w;
        }
        // load B tile
#pragma unroll
        for (int p = 0; p < (BK * BN / 4) / 128; p++) {
            int idx = t + 128 * p;
            int r = idx / (BN / 4), c = idx % (BN / 4);
            *(float4*)&sB[r][c * 4] = *(const float4*)&g_W2t[(size_t)(kt + r) * BN + c * 4];
        }
        __syncthreads();
#pragma unroll
        for (int kk = 0; kk < BK; kk++) {
            float a[4];
#pragma unroll
            for (int q = 0; q < 4; q++) a[q] = sA[kk][rm + q];
            unsigned long long bv[TN / 2];
#pragma unroll
            for (int w = 0; w < TN / 2; w++)
                bv[w] = *(const unsigned long long*)&sB[kk][rn + 2 * w];
#pragma unroll
            for (int q = 0; q < 4; q++) {
                unsigned long long a2;
                unsigned int au = __float_as_uint(a[q]);
                asm("mov.b64 %0, {%1, %1};" : "=l"(a2) : "r"(au));
#pragma unroll
                for (int w = 0; w < TN / 2; w++)
                    asm("fma.rn.f32x2 %0, %1, %2, %0;"
                        : "+l"(acc[q][w]) : "l"(a2), "l"(bv[w]));
            }
        }
        __syncthreads();
    }

#pragma unroll
    for (int q = 0; q < 4; q++) {
        int m = m0 + rm + q;
#pragma unroll
        for (int w = 0; w < TN / 2; w++) {
            unsigned long long v = acc[q][w];
            float lo = __uint_as_float((unsigned int)(v & 0xffffffffull));
            float hi = __uint_as_float((unsigned int)(v >> 32));
            atomicAdd(&g_agg[(size_t)m * BN + rn + 2 * w], lo);
            atomicAdd(&g_agg[(size_t)m * BN + rn + 2 * w + 1], hi);
        }
    }
}

// ---------------- epilogue: out = elu(agg + xs@B2 + x@root + bias) ----------------
__global__ void k_epilogue(const float* __restrict__ xcur,
                           const float* __restrict__ b2,
                           const float* __restrict__ root,
                           const float* __restrict__ bias,
                           float* __restrict__ xnext, int ci, int co)
{
    int idx = blockIdx.x * blockDim.x + threadIdx.x;
    if (idx >= N_NODES * co) return;
    int n = idx / co, o = idx % co;
    float v = g_agg[idx] + bias[o];
    for (int i = 0; i < ci; i++) {
        v += g_xs[n * 64 + i] * b2[i * co + o];
        v += xcur[n * ci + i] * root[i * co + o];
    }
    xnext[idx] = (v > 0.f) ? v : expm1f(v);
}

// ---------------- pooling ----------------
__global__ void k_pool1(const float* __restrict__ x3, const int* __restrict__ n2s) {
    int idx = blockIdx.x * blockDim.x + threadIdx.x;
    if (idx >= N_NODES * 64) return;
    int n = idx / 64, o = idx % 64;
    int s = n2s[n];
    atomicAdd(&g_sub[s * 64 + o], x3[idx]);
    if (o == 0) atomicAdd(&g_subcnt[s], 1.f);
}

__global__ void k_pool2(const int* __restrict__ s2g) {
    int idx = blockIdx.x * blockDim.x + threadIdx.x;
    if (idx >= N_SUB * 64) return;
    int s = idx / 64, o = idx % 64;
    float m = g_sub[idx] / fmaxf(g_subcnt[s], 1.f);
    int g = s2g[s];
    atomicAdd(&g_graph[g * 64 + o], m);
    if (o == 0) atomicAdd(&g_graphcnt[g], 1.f);
}

// ---------------- final MLP (single block) ----------------
__global__ void k_fc(const float* __restrict__ fc1w, const float* __restrict__ fc1b,
                     const float* __restrict__ fc2w, const float* __restrict__ fc2b,
                     const float* __restrict__ fc3w, const float* __restrict__ fc3b,
                     float* __restrict__ out)
{
    __shared__ float hg[32 * 64];
    __shared__ float h1[32 * 32];
    __shared__ float h2[32 * 16];
    int t = threadIdx.x;  // 256
    for (int idx = t; idx < 32 * 64; idx += 256) {
        int g = idx / 64;
        hg[idx] = g_graph[idx] / fmaxf(g_graphcnt[g], 1.f);
    }
    __syncthreads();
    for (int idx = t; idx < 32 * 32; idx += 256) {
        int g = idx / 32, o = idx % 32;
        float v = fc1b[o];
        for (int i = 0; i < 64; i++) v += hg[g * 64 + i] * fc1w[i * 32 + o];
        h1[idx] = (v > 0.f) ? v : expm1f(v);
    }
    __syncthreads();
    for (int idx = t; idx < 32 * 16; idx += 256) {
        int g = idx / 16, o = idx % 16;
        float v = fc2b[o];
        for (int i = 0; i < 32; i++) v += h1[g * 32 + i] * fc2w[i * 16 + o];
        h2[idx] = (v > 0.f) ? v : expm1f(v);
    }
    __syncthreads();
    if (t < 32) {
        float v = fc3b[0];
        for (int i = 0; i < 16; i++) v += h2[t * 16 + i] * fc3w[i];
        out[t] = v;
    }
}

// ---------------- host launch ----------------
extern "C" void kernel_launch(void* const* d_in, const int* in_sizes, int n_in,
                              void* d_out, int out_size)
{
    const float* x     = (const float*)d_in[0];
    const int*   ei    = (const int*)d_in[1];
    const float* eattr = (const float*)d_in[2];
    const int*   n2s   = (const int*)d_in[3];
    const int*   s2g   = (const int*)d_in[4];
    const float* W1[3]   = {(const float*)d_in[5],  (const float*)d_in[11], (const float*)d_in[17]};
    const float* b1[3]   = {(const float*)d_in[6],  (const float*)d_in[12], (const float*)d_in[18]};
    const float* W2[3]   = {(const float*)d_in[7],  (const float*)d_in[13], (const float*)d_in[19]};
    const float* b2[3]   = {(const float*)d_in[8],  (const float*)d_in[14], (const float*)d_in[20]};
    const float* root[3] = {(const float*)d_in[9],  (const float*)d_in[15], (const float*)d_in[21]};
    const float* bias[3] = {(const float*)d_in[10], (const float*)d_in[16], (const float*)d_in[22]};
    const float* fc1w = (const float*)d_in[23];
    const float* fc1b = (const float*)d_in[24];
    const float* fc2w = (const float*)d_in[25];
    const float* fc2b = (const float*)d_in[26];
    const float* fc3w = (const float*)d_in[27];
    const float* fc3b = (const float*)d_in[28];
    float* out = (float*)d_out;

    float *xa, *xb;
    cudaGetSymbolAddress((void**)&xa, g_xa);
    cudaGetSymbolAddress((void**)&xb, g_xb);

    // CSR by dst
    k_zero_rowptr<<<(N_NODES + 256) / 256, 256>>>();
    k_count<<<N_EDGES / 256, 256>>>(ei);
    k_scan<<<1, 1024>>>();
    k_fill<<<N_EDGES / 256, 256>>>(ei);

    const int ci[3] = {16, 32, 64};
    const int co[3] = {32, 64, 64};
    const float* xcur = x;
    float* xnext = xa;

    for (int l = 0; l < 3; l++) {
        int K = 128 * ci[l];
        k_w2t<<<(K * co[l] + 255) / 256, 256>>>(W2[l], ci[l], co[l], K);

        if (l == 0)      k_scatter<16><<<N_NODES, 128>>>(xcur, ei, eattr, W1[l], b1[l]);
        else if (l == 1) k_scatter<32><<<N_NODES, 128>>>(xcur, ei, eattr, W1[l], b1[l]);
        else             k_scatter<64><<<N_NODES, 128>>>(xcur, ei, eattr, W1[l], b1[l]);

        k_zero_agg<<<(N_NODES * co[l] + 255) / 256, 256>>>(N_NODES * co[l]);

        dim3 ggrid(N_NODES / 64, 4);
        int kspl = K / 4;
        if (co[l] == 32) k_gemm<32><<<ggrid, 128>>>(K, kspl);
        else             k_gemm<64><<<ggrid, 128>>>(K, kspl);

        k_epilogue<<<(N_NODES * co[l] + 255) / 256, 256>>>(xcur, b2[l], root[l], bias[l],
                                                           xnext, ci[l], co[l]);
        xcur = xnext;
        xnext = (xnext == xa) ? xb : xa;
    }

    // pooling + MLP head
    k_zero_pools<<<(N_SUB * 64 + 255) / 256, 256>>>();
    k_pool1<<<(N_NODES * 64 + 255) / 256, 256>>>(xcur, n2s);
    k_pool2<<<(N_SUB * 64 + 255) / 256, 256>>>(s2g);
    k_fc<<<1, 256>>>(fc1w, fc1b, fc2w, fc2b, fc3w, fc3b, out);
}

// round 3
// speedup vs baseline: 1.3047x; 1.3047x over previous
#include <cuda_runtime.h>
#include <cstdint>

#define N_NODES 8192
#define N_EDGES 32768
#define HID 128
#define N_SUB 512
#define N_GRAPH 32

// ---------------- device scratch (static; no allocations) ----------------
__device__ float g_S[8192 * 64 * 128];     // [n][i*128+k]; row-major [N, K]
__device__ float g_W2t[8192 * 64];         // [K][co]
__device__ float g_xa[N_NODES * 64];
__device__ float g_xb[N_NODES * 64];
__device__ float g_xs[N_NODES * 64];       // sum of x[src] over incoming edges
__device__ float g_agg[N_NODES * 64];      // GEMM output accumulator
__device__ int   g_rowptr[N_NODES + 1];
__device__ int   g_fill[N_NODES];
__device__ int   g_eperm[N_EDGES];
__device__ float g_sub[N_SUB * 64];
__device__ float g_subcnt[N_SUB];
__device__ float g_graph[N_GRAPH * 64];
__device__ float g_graphcnt[N_GRAPH];

// ---------------- init: zero rowptr + pools ----------------
// NOTE: grid must cover N_SUB*64 = 32768 elements (129 blocks of 256).
__global__ void k_init() {
    int i = blockIdx.x * blockDim.x + threadIdx.x;
    if (i <= N_NODES) g_rowptr[i] = 0;
    if (i < N_SUB * 64)   g_sub[i] = 0.f;
    if (i < N_SUB)        g_subcnt[i] = 0.f;
    if (i < N_GRAPH * 64) g_graph[i] = 0.f;
    if (i < N_GRAPH)      g_graphcnt[i] = 0.f;
}

__global__ void k_count(const int* __restrict__ ei) {
    int e = blockIdx.x * blockDim.x + threadIdx.x;
    if (e < N_EDGES) atomicAdd(&g_rowptr[ei[N_EDGES + e] + 1], 1);
}

// single-block scan over 8192 counts -> exclusive rowptr; also init g_fill
__global__ void k_scan() {
    __shared__ int part[1024];
    int t = threadIdx.x;
    int v[8];
    int run = 0;
#pragma unroll
    for (int q = 0; q < 8; q++) { run += g_rowptr[1 + t * 8 + q]; v[q] = run; }
    part[t] = run;
    __syncthreads();
    int sum = run;
    for (int off = 1; off < 1024; off <<= 1) {
        int other = (t >= off) ? part[t - off] : 0;
        __syncthreads();
        sum += other;
        part[t] = sum;
        __syncthreads();
    }
    int add = sum - run;
#pragma unroll
    for (int q = 0; q < 8; q++) {
        int val = v[q] + add;
        int pos = 1 + t * 8 + q;
        g_rowptr[pos] = val;
        if (pos < N_NODES) g_fill[pos] = val;
    }
    if (t == 0) { g_rowptr[0] = 0; g_fill[0] = 0; }
}

__global__ void k_fill(const int* __restrict__ ei) {
    int e = blockIdx.x * blockDim.x + threadIdx.x;
    if (e < N_EDGES) {
        int d = ei[N_EDGES + e];
        int pos = atomicAdd(&g_fill[d], 1);
        g_eperm[pos] = e;
    }
}

// W2t[(i*128+k)*co + o] = W2[(k*ci + i)*co + o]  AND zero g_agg (fused)
__global__ void k_w2t_zero(const float* __restrict__ W2, int ci, int co, int K) {
    int idx = blockIdx.x * blockDim.x + threadIdx.x;
    if (idx < K * co) {
        int kk = idx / co, o = idx % co;
        int i = kk >> 7, k = kk & 127;
        g_W2t[idx] = W2[(k * ci + i) * co + o];
    }
    if (idx < N_NODES * co) g_agg[idx] = 0.f;
}

// ---------------- scatter: S[n, i*128+k] = sum_{e->n} h[e,k] * x[src_e, i] --------
// One block per node, 128 threads (thread t = hidden channel k). S row in regs.
// Edges staged 4 at a time (one warp each) -> 2 barriers per 4 edges.
template <int CI>
__global__ __launch_bounds__(128) void k_scatter(
    const float* __restrict__ xcur, const int* __restrict__ ei,
    const float* __restrict__ eattr, const float* __restrict__ W1,
    const float* __restrict__ b1)
{
    int n = blockIdx.x;
    int t = threadIdx.x;
    int w = t >> 5, lane = t & 31;
    __shared__ float sx[4][CI];
    __shared__ float sattr[4][5];

    float w1r[5];
#pragma unroll
    for (int j = 0; j < 5; j++) w1r[j] = W1[j * HID + t];
    float b1r = b1[t];

    float sacc[CI];
#pragma unroll
    for (int i = 0; i < CI; i++) sacc[i] = 0.f;
    float xsacc = 0.f;

    int beg = g_rowptr[n], end = g_rowptr[n + 1];
    for (int j0 = beg; j0 < end; j0 += 4) {
        int cnt = min(4, end - j0);
        if (w < cnt) {
            int e = g_eperm[j0 + w];
            int src = ei[e];
            if (lane < 5) sattr[w][lane] = eattr[e * 5 + lane];
#pragma unroll
            for (int i = lane; i < CI; i += 32) sx[w][i] = xcur[src * CI + i];
        }
        __syncthreads();
        for (int c = 0; c < cnt; c++) {
            float h = b1r;
#pragma unroll
            for (int q = 0; q < 5; q++) h += sattr[c][q] * w1r[q];
            h = fmaxf(h, 0.f);
#pragma unroll
            for (int i = 0; i < CI; i++) sacc[i] += h * sx[c][i];
            if (t < CI) xsacc += sx[c][t];
        }
        __syncthreads();
    }

    size_t base = (size_t)n * CI * HID;
#pragma unroll
    for (int i = 0; i < CI; i++) g_S[base + (size_t)i * HID + t] = sacc[i];
    if (t < CI) g_xs[n * 64 + t] = xsacc;
}

// ---------------- GEMM: g_agg[M, BN] += g_S[M, K] @ g_W2t[K, BN] ----------------
// BM=128, BK=16, 128 threads, register tile TM=8 x TN, packed fma.rn.f32x2.
// Split-K over blockIdx.y with atomic accumulation; register-staged prefetch.
template <int BN, int TN>
__global__ __launch_bounds__(128) void k_gemm(int K, int kspl)
{
    constexpr int BM = 128, BK = 16, TM = 8;
    constexpr int NW = TN / 2;
    __shared__ float sA[BK][BM + 4];   // transposed: sA[k][m]
    __shared__ float sB[BK][BN];

    const int t  = threadIdx.x;                 // 128 threads
    const int m0 = blockIdx.x * BM;
    const int k0 = blockIdx.y * kspl;
    const int rm = (t / (BN / TN)) * TM;        // 16 row groups
    const int rn = (t % (BN / TN)) * TN;

    const int a_c4 = t & 3;
    const int a_r0 = t >> 2;
    constexpr int BP = (BK * BN / 4) / 128;     // 2 for BN=64, 1 for BN=32

    unsigned long long acc[TM][NW];
#pragma unroll
    for (int q = 0; q < TM; q++)
#pragma unroll
        for (int wv = 0; wv < NW; wv++) acc[q][wv] = 0ull;

    const int nIter = kspl / BK;
    float4 pa[4];
    float4 pb[BP];

    // prologue: load first tile into regs
    {
        int kt = k0;
#pragma unroll
        for (int p = 0; p < 4; p++)
            pa[p] = *(const float4*)&g_S[(size_t)(m0 + a_r0 + 32 * p) * K + kt + a_c4 * 4];
#pragma unroll
        for (int p = 0; p < BP; p++) {
            int f = t + 128 * p;
            int r = f / (BN / 4), c = f % (BN / 4);
            pb[p] = *(const float4*)&g_W2t[(size_t)(kt + r) * BN + c * 4];
        }
    }

    for (int it = 0; it < nIter; it++) {
        // store staged tile to smem
#pragma unroll
        for (int p = 0; p < 4; p++) {
            int r = a_r0 + 32 * p;
            sA[a_c4 * 4 + 0][r] = pa[p].x;
            sA[a_c4 * 4 + 1][r] = pa[p].y;
            sA[a_c4 * 4 + 2][r] = pa[p].z;
            sA[a_c4 * 4 + 3][r] = pa[p].w;
        }
#pragma unroll
        for (int p = 0; p < BP; p++) {
            int f = t + 128 * p;
            int r = f / (BN / 4), c = f % (BN / 4);
            *(float4*)&sB[r][c * 4] = pb[p];
        }
        __syncthreads();

        // prefetch next tile into regs (hidden under compute)
        if (it + 1 < nIter) {
            int kt = k0 + (it + 1) * BK;
#pragma unroll
            for (int p = 0; p < 4; p++)
                pa[p] = *(const float4*)&g_S[(size_t)(m0 + a_r0 + 32 * p) * K + kt + a_c4 * 4];
#pragma unroll
            for (int p = 0; p < BP; p++) {
                int f = t + 128 * p;
                int r = f / (BN / 4), c = f % (BN / 4);
                pb[p] = *(const float4*)&g_W2t[(size_t)(kt + r) * BN + c * 4];
            }
        }

#pragma unroll
        for (int kk = 0; kk < BK; kk++) {
            float4 a0 = *(const float4*)&sA[kk][rm];
            float4 a1 = *(const float4*)&sA[kk][rm + 4];
            unsigned long long bv[NW];
#pragma unroll
            for (int wv = 0; wv < NW; wv++)
                bv[wv] = *(const unsigned long long*)&sB[kk][rn + 2 * wv];
            float am[TM] = {a0.x, a0.y, a0.z, a0.w, a1.x, a1.y, a1.z, a1.w};
#pragma unroll
            for (int q = 0; q < TM; q++) {
                unsigned long long a2;
                unsigned int au = __float_as_uint(am[q]);
                asm("mov.b64 %0, {%1, %1};" : "=l"(a2) : "r"(au));
#pragma unroll
                for (int wv = 0; wv < NW; wv++)
                    asm("fma.rn.f32x2 %0, %1, %2, %0;"
                        : "+l"(acc[q][wv]) : "l"(a2), "l"(bv[wv]));
            }
        }
        __syncthreads();
    }

#pragma unroll
    for (int q = 0; q < TM; q++) {
        int m = m0 + rm + q;
#pragma unroll
        for (int wv = 0; wv < NW; wv++) {
            unsigned long long v = acc[q][wv];
            float lo = __uint_as_float((unsigned int)(v & 0xffffffffull));
            float hi = __uint_as_float((unsigned int)(v >> 32));
            atomicAdd(&g_agg[(size_t)m * BN + rn + 2 * wv], lo);
            atomicAdd(&g_agg[(size_t)m * BN + rn + 2 * wv + 1], hi);
        }
    }
}

// ---------------- epilogue: out = elu(agg + xs@B2 + x@root + bias) ----------------
__global__ void k_epilogue(const float* __restrict__ xcur,
                           const float* __restrict__ b2,
                           const float* __restrict__ root,
                           const float* __restrict__ bias,
                           float* __restrict__ xnext, int ci, int co)
{
    int idx = blockIdx.x * blockDim.x + threadIdx.x;
    if (idx >= N_NODES * co) return;
    int n = idx / co, o = idx % co;
    float v = g_agg[idx] + bias[o];
    for (int i = 0; i < ci; i++) {
        v += g_xs[n * 64 + i] * b2[i * co + o];
        v += xcur[n * ci + i] * root[i * co + o];
    }
    xnext[idx] = (v > 0.f) ? v : expm1f(v);
}

// ---------------- pooling ----------------
__global__ void k_pool1(const float* __restrict__ x3, const int* __restrict__ n2s) {
    int idx = blockIdx.x * blockDim.x + threadIdx.x;
    if (idx >= N_NODES * 64) return;
    int n = idx / 64, o = idx % 64;
    int s = n2s[n];
    atomicAdd(&g_sub[s * 64 + o], x3[idx]);
    if (o == 0) atomicAdd(&g_subcnt[s], 1.f);
}

__global__ void k_pool2(const int* __restrict__ s2g) {
    int idx = blockIdx.x * blockDim.x + threadIdx.x;
    if (idx >= N_SUB * 64) return;
    int s = idx / 64, o = idx % 64;
    float m = g_sub[idx] / fmaxf(g_subcnt[s], 1.f);
    int g = s2g[s];
    atomicAdd(&g_graph[g * 64 + o], m);
    if (o == 0) atomicAdd(&g_graphcnt[g], 1.f);
}

// ---------------- final MLP (single block) ----------------
__global__ void k_fc(const float* __restrict__ fc1w, const float* __restrict__ fc1b,
                     const float* __restrict__ fc2w, const float* __restrict__ fc2b,
                     const float* __restrict__ fc3w, const float* __restrict__ fc3b,
                     float* __restrict__ out)
{
    __shared__ float hg[32 * 64];
    __shared__ float h1[32 * 32];
    __shared__ float h2[32 * 16];
    int t = threadIdx.x;  // 256
    for (int idx = t; idx < 32 * 64; idx += 256) {
        int g = idx / 64;
        hg[idx] = g_graph[idx] / fmaxf(g_graphcnt[g], 1.f);
    }
    __syncthreads();
    for (int idx = t; idx < 32 * 32; idx += 256) {
        int g = idx / 32, o = idx % 32;
        float v = fc1b[o];
        for (int i = 0; i < 64; i++) v += hg[g * 64 + i] * fc1w[i * 32 + o];
        h1[idx] = (v > 0.f) ? v : expm1f(v);
    }
    __syncthreads();
    for (int idx = t; idx < 32 * 16; idx += 256) {
        int g = idx / 16, o = idx % 16;
        float v = fc2b[o];
        for (int i = 0; i < 32; i++) v += h1[g * 32 + i] * fc2w[i * 16 + o];
        h2[idx] = (v > 0.f) ? v : expm1f(v);
    }
    __syncthreads();
    if (t < 32) {
        float v = fc3b[0];
        for (int i = 0; i < 16; i++) v += h2[t * 16 + i] * fc3w[i];
        out[t] = v;
    }
}

// ---------------- host launch ----------------
extern "C" void kernel_launch(void* const* d_in, const int* in_sizes, int n_in,
                              void* d_out, int out_size)
{
    const float* x     = (const float*)d_in[0];
    const int*   ei    = (const int*)d_in[1];
    const float* eattr = (const float*)d_in[2];
    const int*   n2s   = (const int*)d_in[3];
    const int*   s2g   = (const int*)d_in[4];
    const float* W1[3]   = {(const float*)d_in[5],  (const float*)d_in[11], (const float*)d_in[17]};
    const float* b1[3]   = {(const float*)d_in[6],  (const float*)d_in[12], (const float*)d_in[18]};
    const float* W2[3]   = {(const float*)d_in[7],  (const float*)d_in[13], (const float*)d_in[19]};
    const float* b2[3]   = {(const float*)d_in[8],  (const float*)d_in[14], (const float*)d_in[20]};
    const float* root[3] = {(const float*)d_in[9],  (const float*)d_in[15], (const float*)d_in[21]};
    const float* bias[3] = {(const float*)d_in[10], (const float*)d_in[16], (const float*)d_in[22]};
    const float* fc1w = (const float*)d_in[23];
    const float* fc1b = (const float*)d_in[24];
    const float* fc2w = (const float*)d_in[25];
    const float* fc2b = (const float*)d_in[26];
    const float* fc3w = (const float*)d_in[27];
    const float* fc3b = (const float*)d_in[28];
    float* out = (float*)d_out;

    float *xa, *xb;
    cudaGetSymbolAddress((void**)&xa, g_xa);
    cudaGetSymbolAddress((void**)&xb, g_xb);

    // CSR by dst + pool zeroing.
    // Grid MUST cover N_SUB*64 = 32768 (the round-2 bug: only 8448 covered).
    k_init<<<(N_SUB * 64 + 255) / 256, 256>>>();
    k_count<<<N_EDGES / 256, 256>>>(ei);
    k_scan<<<1, 1024>>>();
    k_fill<<<N_EDGES / 256, 256>>>(ei);

    const int ci[3] = {16, 32, 64};
    const int co[3] = {32, 64, 64};
    const float* xcur = x;
    float* xnext = xa;

    for (int l = 0; l < 3; l++) {
        int K = 128 * ci[l];
        int wz = max(K * co[l], N_NODES * co[l]);
        k_w2t_zero<<<(wz + 255) / 256, 256>>>(W2[l], ci[l], co[l], K);

        if (l == 0)      k_scatter<16><<<N_NODES, 128>>>(xcur, ei, eattr, W1[l], b1[l]);
        else if (l == 1) k_scatter<32><<<N_NODES, 128>>>(xcur, ei, eattr, W1[l], b1[l]);
        else             k_scatter<64><<<N_NODES, 128>>>(xcur, ei, eattr, W1[l], b1[l]);

        const int splitk = 8;
        dim3 ggrid(N_NODES / 128, splitk);
        int kspl = K / splitk;
        if (co[l] == 32) k_gemm<32, 4><<<ggrid, 128>>>(K, kspl);
        else             k_gemm<64, 8><<<ggrid, 128>>>(K, kspl);

        k_epilogue<<<(N_NODES * co[l] + 255) / 256, 256>>>(xcur, b2[l], root[l], bias[l],
                                                           xnext, ci[l], co[l]);
        xcur = xnext;
        xnext = (xnext == xa) ? xb : xa;
    }

    // pooling + MLP head
    k_pool1<<<(N_NODES * 64 + 255) / 256, 256>>>(xcur, n2s);
    k_pool2<<<(N_SUB * 64 + 255) / 256, 256>>>(s2g);
    k_fc<<<1, 256>>>(fc1w, fc1b, fc2w, fc2b, fc3w, fc3b, out);
}

// round 5
// speedup vs baseline: 1.5022x; 1.1514x over previous
#include <cuda_runtime.h>
#include <cuda_bf16.h>
#include <cstdint>

#define N_NODES 8192
#define N_EDGES 32768
#define HID 128
#define N_SUB 512
#define N_GRAPH 32

// ---------------- device scratch (static; no allocations) ----------------
__device__ __nv_bfloat16 g_Shi[8192ull * 8192];   // [n][K] bf16 hi
__device__ __nv_bfloat16 g_Slo[8192ull * 8192];   // [n][K] bf16 lo
__device__ __nv_bfloat16 g_Bhi[8192 * 64];        // [K][co] bf16 hi (k-major)
__device__ __nv_bfloat16 g_Blo[8192 * 64];        // [K][co] bf16 lo
__device__ float g_xa[N_NODES * 64];
__device__ float g_xb[N_NODES * 64];
__device__ float g_xs[N_NODES * 64];
__device__ float g_agg[N_NODES * 64];
__device__ int   g_rowptr[N_NODES + 1];
__device__ int   g_fill[N_NODES];
__device__ int   g_eperm[N_EDGES];
__device__ float g_sub[N_SUB * 64];
__device__ float g_subcnt[N_SUB];
__device__ float g_graph[N_GRAPH * 64];
__device__ float g_graphcnt[N_GRAPH];

// ---------------- warp-MMA helpers (baseline PTX, no arch-suffix gating) --------
__device__ __forceinline__ uint32_t smem_u32(const void* p) {
    uint32_t a;
    asm("{ .reg .u64 t; cvta.to.shared.u64 t, %1; cvt.u32.u64 %0, t; }" : "=r"(a) : "l"(p));
    return a;
}
__device__ __forceinline__ void ldsm_x4(uint32_t& r0, uint32_t& r1, uint32_t& r2,
                                        uint32_t& r3, uint32_t addr) {
    asm volatile("ldmatrix.sync.aligned.m8n8.x4.shared.b16 {%0,%1,%2,%3}, [%4];"
                 : "=r"(r0), "=r"(r1), "=r"(r2), "=r"(r3) : "r"(addr));
}
__device__ __forceinline__ void ldsm_x4t(uint32_t& r0, uint32_t& r1, uint32_t& r2,
                                         uint32_t& r3, uint32_t addr) {
    asm volatile("ldmatrix.sync.aligned.m8n8.x4.trans.shared.b16 {%0,%1,%2,%3}, [%4];"
                 : "=r"(r0), "=r"(r1), "=r"(r2), "=r"(r3) : "r"(addr));
}
__device__ __forceinline__ void mma_bf16(float& d0, float& d1, float& d2, float& d3,
                                         uint32_t a0, uint32_t a1, uint32_t a2, uint32_t a3,
                                         uint32_t b0, uint32_t b1) {
    asm volatile(
        "mma.sync.aligned.m16n8k16.row.col.f32.bf16.bf16.f32 "
        "{%0,%1,%2,%3}, {%4,%5,%6,%7}, {%8,%9}, {%0,%1,%2,%3};"
        : "+f"(d0), "+f"(d1), "+f"(d2), "+f"(d3)
        : "r"(a0), "r"(a1), "r"(a2), "r"(a3), "r"(b0), "r"(b1));
}

// ---------------- init: zero rowptr + pools (grid covers N_SUB*64!) ----------------
__global__ void k_init() {
    int i = blockIdx.x * blockDim.x + threadIdx.x;
    if (i <= N_NODES) g_rowptr[i] = 0;
    if (i < N_SUB * 64)   g_sub[i] = 0.f;
    if (i < N_SUB)        g_subcnt[i] = 0.f;
    if (i < N_GRAPH * 64) g_graph[i] = 0.f;
    if (i < N_GRAPH)      g_graphcnt[i] = 0.f;
}

__global__ void k_count(const int* __restrict__ ei) {
    int e = blockIdx.x * blockDim.x + threadIdx.x;
    if (e < N_EDGES) atomicAdd(&g_rowptr[ei[N_EDGES + e] + 1], 1);
}

__global__ void k_scan() {
    __shared__ int part[1024];
    int t = threadIdx.x;
    int v[8];
    int run = 0;
#pragma unroll
    for (int q = 0; q < 8; q++) { run += g_rowptr[1 + t * 8 + q]; v[q] = run; }
    part[t] = run;
    __syncthreads();
    int sum = run;
    for (int off = 1; off < 1024; off <<= 1) {
        int other = (t >= off) ? part[t - off] : 0;
        __syncthreads();
        sum += other;
        part[t] = sum;
        __syncthreads();
    }
    int add = sum - run;
#pragma unroll
    for (int q = 0; q < 8; q++) {
        int val = v[q] + add;
        int pos = 1 + t * 8 + q;
        g_rowptr[pos] = val;
        if (pos < N_NODES) g_fill[pos] = val;
    }
    if (t == 0) { g_rowptr[0] = 0; g_fill[0] = 0; }
}

__global__ void k_fill(const int* __restrict__ ei) {
    int e = blockIdx.x * blockDim.x + threadIdx.x;
    if (e < N_EDGES) {
        int d = ei[N_EDGES + e];
        int pos = atomicAdd(&g_fill[d], 1);
        g_eperm[pos] = e;
    }
}

// B split: Bhi/Blo[kk][o] (k-major) = bf16 hi/lo of W2[(k*ci+i)*co+o], kk = i*128+k
__global__ void k_bsplit(const float* __restrict__ W2, int ci, int co, int K) {
    int idx = blockIdx.x * blockDim.x + threadIdx.x;
    if (idx >= K * co) return;
    int kk = idx / co, o = idx % co;
    int i = kk >> 7, k = kk & 127;
    float w = W2[(k * ci + i) * co + o];
    __nv_bfloat16 h = __float2bfloat16(w);
    __nv_bfloat16 lo = __float2bfloat16(w - __bfloat162float(h));
    g_Bhi[idx] = h;
    g_Blo[idx] = lo;
}

// ---------------- scatter: S[n, i*128+k] -> bf16 hi/lo ----------------
template <int CI>
__global__ __launch_bounds__(128) void k_scatter(
    const float* __restrict__ xcur, const int* __restrict__ ei,
    const float* __restrict__ eattr, const float* __restrict__ W1,
    const float* __restrict__ b1)
{
    int n = blockIdx.x;
    int t = threadIdx.x;
    int w = t >> 5, lane = t & 31;
    __shared__ float sx[4][CI];
    __shared__ float sattr[4][5];

    float w1r[5];
#pragma unroll
    for (int j = 0; j < 5; j++) w1r[j] = W1[j * HID + t];
    float b1r = b1[t];

    float sacc[CI];
#pragma unroll
    for (int i = 0; i < CI; i++) sacc[i] = 0.f;
    float xsacc = 0.f;

    int beg = g_rowptr[n], end = g_rowptr[n + 1];
    for (int j0 = beg; j0 < end; j0 += 4) {
        int cnt = min(4, end - j0);
        if (w < cnt) {
            int e = g_eperm[j0 + w];
            int src = ei[e];
            if (lane < 5) sattr[w][lane] = eattr[e * 5 + lane];
#pragma unroll
            for (int i = lane; i < CI; i += 32) sx[w][i] = xcur[src * CI + i];
        }
        __syncthreads();
        for (int c = 0; c < cnt; c++) {
            float h = b1r;
#pragma unroll
            for (int q = 0; q < 5; q++) h += sattr[c][q] * w1r[q];
            h = fmaxf(h, 0.f);
#pragma unroll
            for (int i = 0; i < CI; i++) sacc[i] += h * sx[c][i];
            if (t < CI) xsacc += sx[c][t];
        }
        __syncthreads();
    }

    size_t base = (size_t)n * CI * HID;
#pragma unroll
    for (int i = 0; i < CI; i++) {
        float v = sacc[i];
        __nv_bfloat16 h = __float2bfloat16(v);
        __nv_bfloat16 lo = __float2bfloat16(v - __bfloat162float(h));
        g_Shi[base + (size_t)i * HID + t] = h;
        g_Slo[base + (size_t)i * HID + t] = lo;
    }
    if (t < CI) g_xs[n * 64 + t] = xsacc;
}

// ---------------- warp-MMA GEMM: g_agg[M, CO] = S[M, K] @ B[K, CO] ----------------
// bf16 hi/lo 3-product emulation on HMMA. BM=64, BK=32, 8 warps (256 thr).
// Full K per block -> plain stores, no atomics. 128 blocks = one wave.
template <int CO>
__global__ __launch_bounds__(256) void k_gemm_mma(int K)
{
    constexpr int BM = 64, BK = 32;
    constexpr int AP = 40;                 // padded A row (bf16 elems)
    constexpr int BP = CO + 8;             // padded B row
    constexpr int WNR = CO / 2;            // per-warp n range (2 n-warps)
    constexpr int NT = WNR / 8;            // n8 tiles per warp (4 or 2)
    constexpr int NPAIR = NT / 2;          // ldmatrix x4.trans pairs

    __shared__ __nv_bfloat16 sAh[BM][AP];
    __shared__ __nv_bfloat16 sAl[BM][AP];
    __shared__ __nv_bfloat16 sBh[BK][BP];
    __shared__ __nv_bfloat16 sBl[BK][BP];

    const int t = threadIdx.x;
    const int wid = t >> 5, lane = t & 31;
    const int wm = wid & 3;                // 4 m-warps of 16 rows
    const int wn = wid >> 2;               // 2 n-warps
    const int m0 = blockIdx.x * BM;

    const uint32_t sAh_b = smem_u32(sAh), sAl_b = smem_u32(sAl);
    const uint32_t sBh_b = smem_u32(sBh), sBl_b = smem_u32(sBl);

    // global load mapping
    const int a_row = t >> 2, a_cv = t & 3;            // A: 64 rows x 4 vec8
    const int b_row = (CO == 64) ? (t >> 3) : (t >> 2);
    const int b_cv  = (CO == 64) ? (t & 7)  : (t & 3);
    const bool b_act = (CO == 64) ? true : (t < 128);

    float acc[NT][4];
#pragma unroll
    for (int i = 0; i < NT; i++)
#pragma unroll
        for (int j = 0; j < 4; j++) acc[i][j] = 0.f;

    const int nIter = K / BK;
    uint4 pah, pal, pbh, pbl;

    // prologue
    {
        const size_t arow_off = (size_t)(m0 + a_row) * K + a_cv * 8;
        pah = *(const uint4*)&g_Shi[arow_off];
        pal = *(const uint4*)&g_Slo[arow_off];
        if (b_act) {
            size_t boff = (size_t)b_row * CO + b_cv * 8;
            pbh = *(const uint4*)&g_Bhi[boff];
            pbl = *(const uint4*)&g_Blo[boff];
        }
    }

    for (int it = 0; it < nIter; it++) {
        *(uint4*)&sAh[a_row][a_cv * 8] = pah;
        *(uint4*)&sAl[a_row][a_cv * 8] = pal;
        if (b_act) {
            *(uint4*)&sBh[b_row][b_cv * 8] = pbh;
            *(uint4*)&sBl[b_row][b_cv * 8] = pbl;
        }
        __syncthreads();

        if (it + 1 < nIter) {
            int kt = (it + 1) * BK;
            const size_t arow_off = (size_t)(m0 + a_row) * K + kt + a_cv * 8;
            pah = *(const uint4*)&g_Shi[arow_off];
            pal = *(const uint4*)&g_Slo[arow_off];
            if (b_act) {
                size_t boff = (size_t)(kt + b_row) * CO + b_cv * 8;
                pbh = *(const uint4*)&g_Bhi[boff];
                pbl = *(const uint4*)&g_Blo[boff];
            }
        }

#pragma unroll
        for (int ks = 0; ks < 2; ks++) {
            // A fragments (m16 x k16), hi and lo
            uint32_t a_off = ((uint32_t)(wm * 16 + (lane & 15)) * AP +
                              (uint32_t)(ks * 16 + (lane >> 4) * 8)) * 2u;
            uint32_t ah0, ah1, ah2, ah3, al0, al1, al2, al3;
            ldsm_x4(ah0, ah1, ah2, ah3, sAh_b + a_off);
            ldsm_x4(al0, al1, al2, al3, sAl_b + a_off);

#pragma unroll
            for (int p = 0; p < NPAIR; p++) {
                int nb = wn * WNR + p * 16;
                uint32_t b_off = ((uint32_t)(ks * 16 + (lane & 15)) * BP +
                                  (uint32_t)(nb + (lane >> 4) * 8)) * 2u;
                uint32_t bh0, bh1, bh2, bh3, bl0, bl1, bl2, bl3;
                ldsm_x4t(bh0, bh1, bh2, bh3, sBh_b + b_off);
                ldsm_x4t(bl0, bl1, bl2, bl3, sBl_b + b_off);

                float* c0 = acc[p * 2 + 0];
                float* c1 = acc[p * 2 + 1];
                // hi*hi
                mma_bf16(c0[0], c0[1], c0[2], c0[3], ah0, ah1, ah2, ah3, bh0, bh1);
                mma_bf16(c1[0], c1[1], c1[2], c1[3], ah0, ah1, ah2, ah3, bh2, bh3);
                // hi*lo
                mma_bf16(c0[0], c0[1], c0[2], c0[3], ah0, ah1, ah2, ah3, bl0, bl1);
                mma_bf16(c1[0], c1[1], c1[2], c1[3], ah0, ah1, ah2, ah3, bl2, bl3);
                // lo*hi
                mma_bf16(c0[0], c0[1], c0[2], c0[3], al0, al1, al2, al3, bh0, bh1);
                mma_bf16(c1[0], c1[1], c1[2], c1[3], al0, al1, al2, al3, bh2, bh3);
            }
        }
        __syncthreads();
    }

    // store: fragment (m16n8): d0,d1 -> (row0, col0..1); d2,d3 -> (row0+8, ...)
    const int row0 = lane >> 2;
    const int col0 = (lane & 3) * 2;
#pragma unroll
    for (int nt = 0; nt < NT; nt++) {
        int m = m0 + wm * 16 + row0;
        int c = wn * WNR + nt * 8 + col0;
        *(float2*)&g_agg[(size_t)m * CO + c] = make_float2(acc[nt][0], acc[nt][1]);
        *(float2*)&g_agg[(size_t)(m + 8) * CO + c] = make_float2(acc[nt][2], acc[nt][3]);
    }
}

// ---------------- epilogue: out = elu(agg + xs@B2 + x@root + bias) ----------------
__global__ void k_epilogue(const float* __restrict__ xcur,
                           const float* __restrict__ b2,
                           const float* __restrict__ root,
                           const float* __restrict__ bias,
                           float* __restrict__ xnext, int ci, int co)
{
    int idx = blockIdx.x * blockDim.x + threadIdx.x;
    if (idx >= N_NODES * co) return;
    int n = idx / co, o = idx % co;
    float v = g_agg[idx] + bias[o];
    for (int i = 0; i < ci; i++) {
        v += g_xs[n * 64 + i] * b2[i * co + o];
        v += xcur[n * ci + i] * root[i * co + o];
    }
    xnext[idx] = (v > 0.f) ? v : expm1f(v);
}

// ---------------- pooling ----------------
__global__ void k_pool1(const float* __restrict__ x3, const int* __restrict__ n2s) {
    int idx = blockIdx.x * blockDim.x + threadIdx.x;
    if (idx >= N_NODES * 64) return;
    int n = idx / 64, o = idx % 64;
    int s = n2s[n];
    atomicAdd(&g_sub[s * 64 + o], x3[idx]);
    if (o == 0) atomicAdd(&g_subcnt[s], 1.f);
}

__global__ void k_pool2(const int* __restrict__ s2g) {
    int idx = blockIdx.x * blockDim.x + threadIdx.x;
    if (idx >= N_SUB * 64) return;
    int s = idx / 64, o = idx % 64;
    float m = g_sub[idx] / fmaxf(g_subcnt[s], 1.f);
    int g = s2g[s];
    atomicAdd(&g_graph[g * 64 + o], m);
    if (o == 0) atomicAdd(&g_graphcnt[g], 1.f);
}

// ---------------- final MLP (single block) ----------------
__global__ void k_fc(const float* __restrict__ fc1w, const float* __restrict__ fc1b,
                     const float* __restrict__ fc2w, const float* __restrict__ fc2b,
                     const float* __restrict__ fc3w, const float* __restrict__ fc3b,
                     float* __restrict__ out)
{
    __shared__ float hg[32 * 64];
    __shared__ float h1[32 * 32];
    __shared__ float h2[32 * 16];
    int t = threadIdx.x;  // 256
    for (int idx = t; idx < 32 * 64; idx += 256) {
        int g = idx / 64;
        hg[idx] = g_graph[idx] / fmaxf(g_graphcnt[g], 1.f);
    }
    __syncthreads();
    for (int idx = t; idx < 32 * 32; idx += 256) {
        int g = idx / 32, o = idx % 32;
        float v = fc1b[o];
        for (int i = 0; i < 64; i++) v += hg[g * 64 + i] * fc1w[i * 32 + o];
        h1[idx] = (v > 0.f) ? v : expm1f(v);
    }
    __syncthreads();
    for (int idx = t; idx < 32 * 16; idx += 256) {
        int g = idx / 16, o = idx % 16;
        float v = fc2b[o];
        for (int i = 0; i < 32; i++) v += h1[g * 32 + i] * fc2w[i * 16 + o];
        h2[idx] = (v > 0.f) ? v : expm1f(v);
    }
    __syncthreads();
    if (t < 32) {
        float v = fc3b[0];
        for (int i = 0; i < 16; i++) v += h2[t * 16 + i] * fc3w[i];
        out[t] = v;
    }
}

// ---------------- host launch ----------------
extern "C" void kernel_launch(void* const* d_in, const int* in_sizes, int n_in,
                              void* d_out, int out_size)
{
    const float* x     = (const float*)d_in[0];
    const int*   ei    = (const int*)d_in[1];
    const float* eattr = (const float*)d_in[2];
    const int*   n2s   = (const int*)d_in[3];
    const int*   s2g   = (const int*)d_in[4];
    const float* W1[3]   = {(const float*)d_in[5],  (const float*)d_in[11], (const float*)d_in[17]};
    const float* b1[3]   = {(const float*)d_in[6],  (const float*)d_in[12], (const float*)d_in[18]};
    const float* W2[3]   = {(const float*)d_in[7],  (const float*)d_in[13], (const float*)d_in[19]};
    const float* b2[3]   = {(const float*)d_in[8],  (const float*)d_in[14], (const float*)d_in[20]};
    const float* root[3] = {(const float*)d_in[9],  (const float*)d_in[15], (const float*)d_in[21]};
    const float* bias[3] = {(const float*)d_in[10], (const float*)d_in[16], (const float*)d_in[22]};
    const float* fc1w = (const float*)d_in[23];
    const float* fc1b = (const float*)d_in[24];
    const float* fc2w = (const float*)d_in[25];
    const float* fc2b = (const float*)d_in[26];
    const float* fc3w = (const float*)d_in[27];
    const float* fc3b = (const float*)d_in[28];
    float* out = (float*)d_out;

    float *xa, *xb;
    cudaGetSymbolAddress((void**)&xa, g_xa);
    cudaGetSymbolAddress((void**)&xb, g_xb);

    // CSR by dst + pool zeroing (grid covers N_SUB*64)
    k_init<<<(N_SUB * 64 + 255) / 256, 256>>>();
    k_count<<<N_EDGES / 256, 256>>>(ei);
    k_scan<<<1, 1024>>>();
    k_fill<<<N_EDGES / 256, 256>>>(ei);

    const int ci[3] = {16, 32, 64};
    const int co[3] = {32, 64, 64};
    const float* xcur = x;
    float* xnext = xa;

    for (int l = 0; l < 3; l++) {
        int K = 128 * ci[l];
        k_bsplit<<<(K * co[l] + 255) / 256, 256>>>(W2[l], ci[l], co[l], K);

        if (l == 0)      k_scatter<16><<<N_NODES, 128>>>(xcur, ei, eattr, W1[l], b1[l]);
        else if (l == 1) k_scatter<32><<<N_NODES, 128>>>(xcur, ei, eattr, W1[l], b1[l]);
        else             k_scatter<64><<<N_NODES, 128>>>(xcur, ei, eattr, W1[l], b1[l]);

        if (co[l] == 32) k_gemm_mma<32><<<N_NODES / 64, 256>>>(K);
        else             k_gemm_mma<64><<<N_NODES / 64, 256>>>(K);

        k_epilogue<<<(N_NODES * co[l] + 255) / 256, 256>>>(xcur, b2[l], root[l], bias[l],
                                                           xnext, ci[l], co[l]);
        xcur = xnext;
        xnext = (xnext == xa) ? xb : xa;
    }

    // pooling + MLP head
    k_pool1<<<(N_NODES * 64 + 255) / 256, 256>>>(xcur, n2s);
    k_pool2<<<(N_SUB * 64 + 255) / 256, 256>>>(s2g);
    k_fc<<<1, 256>>>(fc1w, fc1b, fc2w, fc2b, fc3w, fc3b, out);
}

// round 6
// speedup vs baseline: 2.0705x; 1.3783x over previous
#include <cuda_runtime.h>
#include <cuda_bf16.h>
#include <cstdint>

#define N_NODES 8192
#define N_EDGES 32768
#define HID 128
#define N_SUB 512
#define N_GRAPH 32

// K' per layer (K + 2*ci, padded to multiple of 64)
#define KP0 2112
#define KP1 4160
#define KP2 8320
// B' buffer offsets (elems)
#define BOFF0 0
#define BOFF1 67584            // 2112*32
#define BOFF2 333824           // 67584 + 4160*64
#define BTOT  866304           // 333824 + 8320*64

// ---------------- device scratch (static; no allocations) ----------------
__device__ __nv_bfloat16 g_Shi[8192ull * 8320];   // [n][K'] bf16 hi
__device__ __nv_bfloat16 g_Slo[8192ull * 8320];   // [n][K'] bf16 lo
__device__ __nv_bfloat16 g_Bhi[BTOT];             // [K'][co] per layer, k-major
__device__ __nv_bfloat16 g_Blo[BTOT];
__device__ float g_xa[N_NODES * 64];
__device__ float g_xb[N_NODES * 64];
__device__ int   g_rowptr[N_NODES + 1];
__device__ int   g_fill[N_NODES];
__device__ int   g_eperm[N_EDGES];
__device__ float g_sub[N_SUB * 64];
__device__ float g_subcnt[N_SUB];
__device__ float g_graph[N_GRAPH * 64];
__device__ float g_graphcnt[N_GRAPH];

// ---------------- PTX helpers (baseline ISA only; no arch-suffix gating) --------
__device__ __forceinline__ uint32_t smem_u32(const void* p) {
    uint32_t a;
    asm("{ .reg .u64 t; cvta.to.shared.u64 t, %1; cvt.u32.u64 %0, t; }" : "=r"(a) : "l"(p));
    return a;
}
__device__ __forceinline__ void ldsm_x4(uint32_t& r0, uint32_t& r1, uint32_t& r2,
                                        uint32_t& r3, uint32_t addr) {
    asm volatile("ldmatrix.sync.aligned.m8n8.x4.shared.b16 {%0,%1,%2,%3}, [%4];"
                 : "=r"(r0), "=r"(r1), "=r"(r2), "=r"(r3) : "r"(addr));
}
__device__ __forceinline__ void ldsm_x4t(uint32_t& r0, uint32_t& r1, uint32_t& r2,
                                         uint32_t& r3, uint32_t addr) {
    asm volatile("ldmatrix.sync.aligned.m8n8.x4.trans.shared.b16 {%0,%1,%2,%3}, [%4];"
                 : "=r"(r0), "=r"(r1), "=r"(r2), "=r"(r3) : "r"(addr));
}
__device__ __forceinline__ void mma_bf16(float& d0, float& d1, float& d2, float& d3,
                                         uint32_t a0, uint32_t a1, uint32_t a2, uint32_t a3,
                                         uint32_t b0, uint32_t b1) {
    asm volatile(
        "mma.sync.aligned.m16n8k16.row.col.f32.bf16.bf16.f32 "
        "{%0,%1,%2,%3}, {%4,%5,%6,%7}, {%8,%9}, {%0,%1,%2,%3};"
        : "+f"(d0), "+f"(d1), "+f"(d2), "+f"(d3)
        : "r"(a0), "r"(a1), "r"(a2), "r"(a3), "r"(b0), "r"(b1));
}
#define CP_ASYNC16(dst, src) \
    asm volatile("cp.async.cg.shared.global [%0], [%1], 16;" :: "r"(dst), "l"(src))
#define CP_COMMIT() asm volatile("cp.async.commit_group;" ::: "memory")
#define CP_WAIT0()  asm volatile("cp.async.wait_group 0;" ::: "memory")

// ---------------- init: zero rowptr + pools (grid covers N_SUB*64!) ----------------
__global__ void k_init() {
    int i = blockIdx.x * blockDim.x + threadIdx.x;
    if (i <= N_NODES) g_rowptr[i] = 0;
    if (i < N_SUB * 64)   g_sub[i] = 0.f;
    if (i < N_SUB)        g_subcnt[i] = 0.f;
    if (i < N_GRAPH * 64) g_graph[i] = 0.f;
    if (i < N_GRAPH)      g_graphcnt[i] = 0.f;
}

__global__ void k_count(const int* __restrict__ ei) {
    int e = blockIdx.x * blockDim.x + threadIdx.x;
    if (e < N_EDGES) atomicAdd(&g_rowptr[ei[N_EDGES + e] + 1], 1);
}

__global__ void k_scan() {
    __shared__ int part[1024];
    int t = threadIdx.x;
    int v[8];
    int run = 0;
#pragma unroll
    for (int q = 0; q < 8; q++) { run += g_rowptr[1 + t * 8 + q]; v[q] = run; }
    part[t] = run;
    __syncthreads();
    int sum = run;
    for (int off = 1; off < 1024; off <<= 1) {
        int other = (t >= off) ? part[t - off] : 0;
        __syncthreads();
        sum += other;
        part[t] = sum;
        __syncthreads();
    }
    int add = sum - run;
#pragma unroll
    for (int q = 0; q < 8; q++) {
        int val = v[q] + add;
        int pos = 1 + t * 8 + q;
        g_rowptr[pos] = val;
        if (pos < N_NODES) g_fill[pos] = val;
    }
    if (t == 0) { g_rowptr[0] = 0; g_fill[0] = 0; }
}

__global__ void k_fill(const int* __restrict__ ei) {
    int e = blockIdx.x * blockDim.x + threadIdx.x;
    if (e < N_EDGES) {
        int d = ei[N_EDGES + e];
        int pos = atomicAdd(&g_fill[d], 1);
        g_eperm[pos] = e;
    }
}

// ---------------- B' split for all 3 layers in one kernel ----------------
// B'[kk][o]: kk<K -> W2[(k*ci+i)*co+o] (kk=i*128+k); K..K+ci -> b2; ..K+2ci -> root; pad 0
__global__ void k_bsplit_all(
    const float* __restrict__ W2_0, const float* __restrict__ b2_0, const float* __restrict__ rt_0,
    const float* __restrict__ W2_1, const float* __restrict__ b2_1, const float* __restrict__ rt_1,
    const float* __restrict__ W2_2, const float* __restrict__ b2_2, const float* __restrict__ rt_2)
{
    int idx = blockIdx.x * blockDim.x + threadIdx.x;
    if (idx >= BTOT) return;
    int rel, ci, co, K;
    const float *W2, *b2, *rt;
    if (idx < BOFF1)      { rel = idx;         ci = 16; co = 32; K = 2048; W2 = W2_0; b2 = b2_0; rt = rt_0; }
    else if (idx < BOFF2) { rel = idx - BOFF1; ci = 32; co = 64; K = 4096; W2 = W2_1; b2 = b2_1; rt = rt_1; }
    else                  { rel = idx - BOFF2; ci = 64; co = 64; K = 8192; W2 = W2_2; b2 = b2_2; rt = rt_2; }
    int kk = rel / co, o = rel % co;
    float w;
    if (kk < K) {
        int i = kk >> 7, k = kk & 127;
        w = W2[(k * ci + i) * co + o];
    } else if (kk < K + ci) {
        w = b2[(kk - K) * co + o];
    } else if (kk < K + 2 * ci) {
        w = rt[(kk - K - ci) * co + o];
    } else {
        w = 0.f;
    }
    __nv_bfloat16 h = __float2bfloat16(w);
    __nv_bfloat16 lo = __float2bfloat16(w - __bfloat162float(h));
    g_Bhi[idx] = h;
    g_Blo[idx] = lo;
}

// ---------------- scatter: S'[n] = [S | xs | x | 0pad] as bf16 hi/lo ----------------
template <int CI>
__global__ __launch_bounds__(128) void k_scatter(
    const float* __restrict__ xcur, const int* __restrict__ ei,
    const float* __restrict__ eattr, const float* __restrict__ W1,
    const float* __restrict__ b1, int KP)
{
    constexpr int K = CI * 128;
    int n = blockIdx.x;
    int t = threadIdx.x;
    int w = t >> 5, lane = t & 31;
    __shared__ float sx[4][CI];
    __shared__ float sattr[4][5];

    float w1r[5];
#pragma unroll
    for (int j = 0; j < 5; j++) w1r[j] = W1[j * HID + t];
    float b1r = b1[t];

    float sacc[CI];
#pragma unroll
    for (int i = 0; i < CI; i++) sacc[i] = 0.f;
    float xsacc = 0.f;

    int beg = g_rowptr[n], end = g_rowptr[n + 1];
    for (int j0 = beg; j0 < end; j0 += 4) {
        int cnt = min(4, end - j0);
        if (w < cnt) {
            int e = g_eperm[j0 + w];
            int src = ei[e];
            if (lane < 5) sattr[w][lane] = eattr[e * 5 + lane];
#pragma unroll
            for (int i = lane; i < CI; i += 32) sx[w][i] = xcur[src * CI + i];
        }
        __syncthreads();
        for (int c = 0; c < cnt; c++) {
            float h = b1r;
#pragma unroll
            for (int q = 0; q < 5; q++) h += sattr[c][q] * w1r[q];
            h = fmaxf(h, 0.f);
#pragma unroll
            for (int i = 0; i < CI; i++) sacc[i] += h * sx[c][i];
            if (t < CI) xsacc += sx[c][t];
        }
        __syncthreads();
    }

    size_t base = (size_t)n * KP;
#pragma unroll
    for (int i = 0; i < CI; i++) {
        float v = sacc[i];
        __nv_bfloat16 h = __float2bfloat16(v);
        __nv_bfloat16 lo = __float2bfloat16(v - __bfloat162float(h));
        g_Shi[base + (size_t)i * HID + t] = h;
        g_Slo[base + (size_t)i * HID + t] = lo;
    }
    // appended columns: [K, K+CI) = xs, [K+CI, K+2CI) = x, rest zero pad
    int ext = KP - K;
    if (t < ext) {
        float v;
        if (t < CI) v = xsacc;
        else if (t < 2 * CI) v = xcur[n * CI + (t - CI)];
        else v = 0.f;
        __nv_bfloat16 h = __float2bfloat16(v);
        __nv_bfloat16 lo = __float2bfloat16(v - __bfloat162float(h));
        g_Shi[base + K + t] = h;
        g_Slo[base + K + t] = lo;
    }
}

// ---------------- fused GEMM + epilogue ----------------
// xnext[M, CO] = elu( S'[M, K'] @ B'[K', CO] + bias )
// BM=64, BK=64, 8 warps; 2-stage cp.async pipeline; bf16 hi/lo 3-product HMMA.
template <int CO>
__global__ __launch_bounds__(256) void k_gemm_mma(int KP, int boff,
                                                  float* __restrict__ xnext,
                                                  const float* __restrict__ bias)
{
    constexpr int AP = 72;                 // padded A row (bf16 elems), 144B
    constexpr int BP = CO + 8;             // padded B row
    constexpr int WNR = CO / 2;            // per n-warp range
    constexpr int NT = WNR / 8;
    constexpr int NPAIR = NT / 2;
    constexpr uint32_t AH_OFF = 0;
    constexpr uint32_t AL_OFF = 64 * AP * 2;               // 9216
    constexpr uint32_t BH_OFF = AL_OFF * 2;                // 18432
    constexpr uint32_t BL_OFF = BH_OFF + 64 * BP * 2;
    constexpr uint32_t STAGE = BL_OFF + 64 * BP * 2;

    extern __shared__ char smem[];
    const uint32_t sb = smem_u32(smem);

    const int t = threadIdx.x;
    const int wid = t >> 5, lane = t & 31;
    const int wm = wid & 3;
    const int wn = wid >> 2;
    const int m0 = blockIdx.x * 64;

    float acc[NT][4];
#pragma unroll
    for (int i = 0; i < NT; i++)
#pragma unroll
        for (int j = 0; j < 4; j++) acc[i][j] = 0.f;

    const int nIter = KP / 64;

    // cp.async issue for one stage at k-offset kt
    auto issue = [&](int sg, int kt) {
        uint32_t s0 = sb + sg * STAGE;
        // A hi/lo: 512 chunks each; chunk c: row=c>>3, col16=c&7
#pragma unroll
        for (int p = 0; p < 2; p++) {
            int c = t + 256 * p;
            int row = c >> 3, cc = c & 7;
            uint32_t d = s0 + (uint32_t)(row * AP + cc * 8) * 2u;
            const __nv_bfloat16* sh = &g_Shi[(size_t)(m0 + row) * KP + kt + cc * 8];
            const __nv_bfloat16* sl = &g_Slo[(size_t)(m0 + row) * KP + kt + cc * 8];
            CP_ASYNC16(d + AH_OFF, sh);
            CP_ASYNC16(d + AL_OFF, sl);
        }
        if (CO == 64) {
#pragma unroll
            for (int p = 0; p < 2; p++) {
                int c = t + 256 * p;
                int row = c >> 3, cc = c & 7;
                uint32_t d = s0 + (uint32_t)(row * BP + cc * 8) * 2u;
                const __nv_bfloat16* bh = &g_Bhi[boff + (size_t)(kt + row) * CO + cc * 8];
                const __nv_bfloat16* bl = &g_Blo[boff + (size_t)(kt + row) * CO + cc * 8];
                CP_ASYNC16(d + BH_OFF, bh);
                CP_ASYNC16(d + BL_OFF, bl);
            }
        } else {
            // CO=32: 256 chunks; chunk c: row=c>>2, col16=c&3
            int c = t;
            int row = c >> 2, cc = c & 3;
            uint32_t d = s0 + (uint32_t)(row * BP + cc * 8) * 2u;
            const __nv_bfloat16* bh = &g_Bhi[boff + (size_t)(kt + row) * CO + cc * 8];
            const __nv_bfloat16* bl = &g_Blo[boff + (size_t)(kt + row) * CO + cc * 8];
            CP_ASYNC16(d + BH_OFF, bh);
            CP_ASYNC16(d + BL_OFF, bl);
        }
    };

    issue(0, 0);
    CP_COMMIT();

    for (int it = 0; it < nIter; it++) {
        CP_WAIT0();
        __syncthreads();
        if (it + 1 < nIter) {
            issue((it + 1) & 1, (it + 1) * 64);
            CP_COMMIT();
        }

        uint32_t s0 = sb + (it & 1) * STAGE;
#pragma unroll
        for (int ks = 0; ks < 4; ks++) {
            uint32_t a_off = s0 + (uint32_t)((wm * 16 + (lane & 15)) * AP +
                                             ks * 16 + (lane >> 4) * 8) * 2u;
            uint32_t ah0, ah1, ah2, ah3, al0, al1, al2, al3;
            ldsm_x4(ah0, ah1, ah2, ah3, a_off + AH_OFF);
            ldsm_x4(al0, al1, al2, al3, a_off + AL_OFF);

#pragma unroll
            for (int p = 0; p < NPAIR; p++) {
                int nb = wn * WNR + p * 16;
                uint32_t b_off = s0 + (uint32_t)((ks * 16 + (lane & 15)) * BP +
                                                 nb + (lane >> 4) * 8) * 2u;
                uint32_t bh0, bh1, bh2, bh3, bl0, bl1, bl2, bl3;
                ldsm_x4t(bh0, bh1, bh2, bh3, b_off + BH_OFF);
                ldsm_x4t(bl0, bl1, bl2, bl3, b_off + BL_OFF);

                float* c0 = acc[p * 2 + 0];
                float* c1 = acc[p * 2 + 1];
                mma_bf16(c0[0], c0[1], c0[2], c0[3], ah0, ah1, ah2, ah3, bh0, bh1);
                mma_bf16(c1[0], c1[1], c1[2], c1[3], ah0, ah1, ah2, ah3, bh2, bh3);
                mma_bf16(c0[0], c0[1], c0[2], c0[3], ah0, ah1, ah2, ah3, bl0, bl1);
                mma_bf16(c1[0], c1[1], c1[2], c1[3], ah0, ah1, ah2, ah3, bl2, bl3);
                mma_bf16(c0[0], c0[1], c0[2], c0[3], al0, al1, al2, al3, bh0, bh1);
                mma_bf16(c1[0], c1[1], c1[2], c1[3], al0, al1, al2, al3, bh2, bh3);
            }
        }
        __syncthreads();
    }

    // fused epilogue: elu(acc + bias) -> xnext
    const int row0 = lane >> 2;
    const int col0 = (lane & 3) * 2;
#pragma unroll
    for (int nt = 0; nt < NT; nt++) {
        int m = m0 + wm * 16 + row0;
        int c = wn * WNR + nt * 8 + col0;
        float b0 = bias[c], b1v = bias[c + 1];
        float v0 = acc[nt][0] + b0, v1 = acc[nt][1] + b1v;
        float v2 = acc[nt][2] + b0, v3 = acc[nt][3] + b1v;
        v0 = (v0 > 0.f) ? v0 : expm1f(v0);
        v1 = (v1 > 0.f) ? v1 : expm1f(v1);
        v2 = (v2 > 0.f) ? v2 : expm1f(v2);
        v3 = (v3 > 0.f) ? v3 : expm1f(v3);
        *(float2*)&xnext[(size_t)m * CO + c] = make_float2(v0, v1);
        *(float2*)&xnext[(size_t)(m + 8) * CO + c] = make_float2(v2, v3);
    }
}

// ---------------- pooling ----------------
__global__ void k_pool1(const float* __restrict__ x3, const int* __restrict__ n2s) {
    int idx = blockIdx.x * blockDim.x + threadIdx.x;
    if (idx >= N_NODES * 64) return;
    int n = idx / 64, o = idx % 64;
    int s = n2s[n];
    atomicAdd(&g_sub[s * 64 + o], x3[idx]);
    if (o == 0) atomicAdd(&g_subcnt[s], 1.f);
}

__global__ void k_pool2(const int* __restrict__ s2g) {
    int idx = blockIdx.x * blockDim.x + threadIdx.x;
    if (idx >= N_SUB * 64) return;
    int s = idx / 64, o = idx % 64;
    float m = g_sub[idx] / fmaxf(g_subcnt[s], 1.f);
    int g = s2g[s];
    atomicAdd(&g_graph[g * 64 + o], m);
    if (o == 0) atomicAdd(&g_graphcnt[g], 1.f);
}

// ---------------- final MLP (single block) ----------------
__global__ void k_fc(const float* __restrict__ fc1w, const float* __restrict__ fc1b,
                     const float* __restrict__ fc2w, const float* __restrict__ fc2b,
                     const float* __restrict__ fc3w, const float* __restrict__ fc3b,
                     float* __restrict__ out)
{
    __shared__ float hg[32 * 64];
    __shared__ float h1[32 * 32];
    __shared__ float h2[32 * 16];
    int t = threadIdx.x;  // 256
    for (int idx = t; idx < 32 * 64; idx += 256) {
        int g = idx / 64;
        hg[idx] = g_graph[idx] / fmaxf(g_graphcnt[g], 1.f);
    }
    __syncthreads();
    for (int idx = t; idx < 32 * 32; idx += 256) {
        int g = idx / 32, o = idx % 32;
        float v = fc1b[o];
        for (int i = 0; i < 64; i++) v += hg[g * 64 + i] * fc1w[i * 32 + o];
        h1[idx] = (v > 0.f) ? v : expm1f(v);
    }
    __syncthreads();
    for (int idx = t; idx < 32 * 16; idx += 256) {
        int g = idx / 16, o = idx % 16;
        float v = fc2b[o];
        for (int i = 0; i < 32; i++) v += h1[g * 32 + i] * fc2w[i * 16 + o];
        h2[idx] = (v > 0.f) ? v : expm1f(v);
    }
    __syncthreads();
    if (t < 32) {
        float v = fc3b[0];
        for (int i = 0; i < 16; i++) v += h2[t * 16 + i] * fc3w[i];
        out[t] = v;
    }
}

// ---------------- host launch ----------------
extern "C" void kernel_launch(void* const* d_in, const int* in_sizes, int n_in,
                              void* d_out, int out_size)
{
    const float* x     = (const float*)d_in[0];
    const int*   ei    = (const int*)d_in[1];
    const float* eattr = (const float*)d_in[2];
    const int*   n2s   = (const int*)d_in[3];
    const int*   s2g   = (const int*)d_in[4];
    const float* W1[3]   = {(const float*)d_in[5],  (const float*)d_in[11], (const float*)d_in[17]};
    const float* b1[3]   = {(const float*)d_in[6],  (const float*)d_in[12], (const float*)d_in[18]};
    const float* W2[3]   = {(const float*)d_in[7],  (const float*)d_in[13], (const float*)d_in[19]};
    const float* b2[3]   = {(const float*)d_in[8],  (const float*)d_in[14], (const float*)d_in[20]};
    const float* root[3] = {(const float*)d_in[9],  (const float*)d_in[15], (const float*)d_in[21]};
    const float* bias[3] = {(const float*)d_in[10], (const float*)d_in[16], (const float*)d_in[22]};
    const float* fc1w = (const float*)d_in[23];
    const float* fc1b = (const float*)d_in[24];
    const float* fc2w = (const float*)d_in[25];
    const float* fc2b = (const float*)d_in[26];
    const float* fc3w = (const float*)d_in[27];
    const float* fc3b = (const float*)d_in[28];
    float* out = (float*)d_out;

    float *xa, *xb;
    cudaGetSymbolAddress((void**)&xa, g_xa);
    cudaGetSymbolAddress((void**)&xb, g_xb);

    // dynamic smem: CO=64 -> 73728B, CO=32 -> 57344B
    static bool attr_set = false;
    if (!attr_set) {
        cudaFuncSetAttribute(k_gemm_mma<64>, cudaFuncAttributeMaxDynamicSharedMemorySize, 73728);
        cudaFuncSetAttribute(k_gemm_mma<32>, cudaFuncAttributeMaxDynamicSharedMemorySize, 57344);
        attr_set = true;
    }

    // CSR by dst + pool zeroing (grid covers N_SUB*64)
    k_init<<<(N_SUB * 64 + 255) / 256, 256>>>();
    k_count<<<N_EDGES / 256, 256>>>(ei);
    k_scan<<<1, 1024>>>();
    k_fill<<<N_EDGES / 256, 256>>>(ei);
    k_bsplit_all<<<(BTOT + 255) / 256, 256>>>(W2[0], b2[0], root[0],
                                              W2[1], b2[1], root[1],
                                              W2[2], b2[2], root[2]);

    const int KP[3] = {KP0, KP1, KP2};
    const int BOFF[3] = {BOFF0, BOFF1, BOFF2};
    const float* xcur = x;
    float* xnext = xa;

    for (int l = 0; l < 3; l++) {
        if (l == 0)      k_scatter<16><<<N_NODES, 128>>>(xcur, ei, eattr, W1[l], b1[l], KP[l]);
        else if (l == 1) k_scatter<32><<<N_NODES, 128>>>(xcur, ei, eattr, W1[l], b1[l], KP[l]);
        else             k_scatter<64><<<N_NODES, 128>>>(xcur, ei, eattr, W1[l], b1[l], KP[l]);

        if (l == 0)
            k_gemm_mma<32><<<N_NODES / 64, 256, 57344>>>(KP[l], BOFF[l], xnext, bias[l]);
        else
            k_gemm_mma<64><<<N_NODES / 64, 256, 73728>>>(KP[l], BOFF[l], xnext, bias[l]);

        xcur = xnext;
        xnext = (xnext == xa) ? xb : xa;
    }

    // pooling + MLP head
    k_pool1<<<(N_NODES * 64 + 255) / 256, 256>>>(xcur, n2s);
    k_pool2<<<(N_SUB * 64 + 255) / 256, 256>>>(s2g);
    k_fc<<<1, 256>>>(fc1w, fc1b, fc2w, fc2b, fc3w, fc3b, out);
}

// round 7
// speedup vs baseline: 2.4215x; 1.1695x over previous
#include <cuda_runtime.h>
#include <cuda_bf16.h>
#include <cstdint>

#define N_NODES 8192
#define N_EDGES 32768
#define HID 128
#define N_SUB 512
#define N_GRAPH 32

// K' per layer (K + 2*ci, padded to multiple of 64)
#define KP0 2112
#define KP1 4160
#define KP2 8320
// B' buffer offsets (elems)
#define BOFF0 0
#define BOFF1 67584            // 2112*32
#define BOFF2 333824           // 67584 + 4160*64
#define BTOT  866304           // 333824 + 8320*64

// ---------------- device scratch (static; no allocations) ----------------
__device__ __nv_bfloat16 g_Shi[8192ull * 8320];   // [n][K'] bf16 hi
__device__ __nv_bfloat16 g_Slo[8192ull * 8320];   // [n][K'] bf16 lo
__device__ __nv_bfloat16 g_Bhi[BTOT];             // [K'][co] per layer, k-major
__device__ __nv_bfloat16 g_Blo[BTOT];
__device__ float g_xa[N_NODES * 64];
__device__ float g_xb[N_NODES * 64];
__device__ int   g_rowptr[N_NODES + 1];
__device__ int   g_fill[N_NODES];
__device__ int   g_eperm[N_EDGES];
__device__ float g_sub[N_SUB * 64];
__device__ float g_subcnt[N_SUB];
__device__ float g_graph[N_GRAPH * 64];
__device__ float g_graphcnt[N_GRAPH];

// ---------------- PTX helpers (baseline ISA only; no arch-suffix gating) --------
__device__ __forceinline__ uint32_t smem_u32(const void* p) {
    uint32_t a;
    asm("{ .reg .u64 t; cvta.to.shared.u64 t, %1; cvt.u32.u64 %0, t; }" : "=r"(a) : "l"(p));
    return a;
}
__device__ __forceinline__ void ldsm_x4(uint32_t& r0, uint32_t& r1, uint32_t& r2,
                                        uint32_t& r3, uint32_t addr) {
    asm volatile("ldmatrix.sync.aligned.m8n8.x4.shared.b16 {%0,%1,%2,%3}, [%4];"
                 : "=r"(r0), "=r"(r1), "=r"(r2), "=r"(r3) : "r"(addr));
}
__device__ __forceinline__ void ldsm_x4t(uint32_t& r0, uint32_t& r1, uint32_t& r2,
                                         uint32_t& r3, uint32_t addr) {
    asm volatile("ldmatrix.sync.aligned.m8n8.x4.trans.shared.b16 {%0,%1,%2,%3}, [%4];"
                 : "=r"(r0), "=r"(r1), "=r"(r2), "=r"(r3) : "r"(addr));
}
__device__ __forceinline__ void mma_bf16(float& d0, float& d1, float& d2, float& d3,
                                         uint32_t a0, uint32_t a1, uint32_t a2, uint32_t a3,
                                         uint32_t b0, uint32_t b1) {
    asm volatile(
        "mma.sync.aligned.m16n8k16.row.col.f32.bf16.bf16.f32 "
        "{%0,%1,%2,%3}, {%4,%5,%6,%7}, {%8,%9}, {%0,%1,%2,%3};"
        : "+f"(d0), "+f"(d1), "+f"(d2), "+f"(d3)
        : "r"(a0), "r"(a1), "r"(a2), "r"(a3), "r"(b0), "r"(b1));
}
#define CP_ASYNC16(dst, src) \
    asm volatile("cp.async.cg.shared.global [%0], [%1], 16;" :: "r"(dst), "l"(src))
#define CP_COMMIT() asm volatile("cp.async.commit_group;" ::: "memory")
#define CP_WAIT2()  asm volatile("cp.async.wait_group 2;" ::: "memory")

// ---------------- init: zero rowptr + pools (grid covers N_SUB*64!) ----------------
__global__ void k_init() {
    int i = blockIdx.x * blockDim.x + threadIdx.x;
    if (i <= N_NODES) g_rowptr[i] = 0;
    if (i < N_SUB * 64)   g_sub[i] = 0.f;
    if (i < N_SUB)        g_subcnt[i] = 0.f;
    if (i < N_GRAPH * 64) g_graph[i] = 0.f;
    if (i < N_GRAPH)      g_graphcnt[i] = 0.f;
}

__global__ void k_count(const int* __restrict__ ei) {
    int e = blockIdx.x * blockDim.x + threadIdx.x;
    if (e < N_EDGES) atomicAdd(&g_rowptr[ei[N_EDGES + e] + 1], 1);
}

__global__ void k_scan() {
    __shared__ int part[1024];
    int t = threadIdx.x;
    int v[8];
    int run = 0;
#pragma unroll
    for (int q = 0; q < 8; q++) { run += g_rowptr[1 + t * 8 + q]; v[q] = run; }
    part[t] = run;
    __syncthreads();
    int sum = run;
    for (int off = 1; off < 1024; off <<= 1) {
        int other = (t >= off) ? part[t - off] : 0;
        __syncthreads();
        sum += other;
        part[t] = sum;
        __syncthreads();
    }
    int add = sum - run;
#pragma unroll
    for (int q = 0; q < 8; q++) {
        int val = v[q] + add;
        int pos = 1 + t * 8 + q;
        g_rowptr[pos] = val;
        if (pos < N_NODES) g_fill[pos] = val;
    }
    if (t == 0) { g_rowptr[0] = 0; g_fill[0] = 0; }
}

__global__ void k_fill(const int* __restrict__ ei) {
    int e = blockIdx.x * blockDim.x + threadIdx.x;
    if (e < N_EDGES) {
        int d = ei[N_EDGES + e];
        int pos = atomicAdd(&g_fill[d], 1);
        g_eperm[pos] = e;
    }
}

// ---------------- B' split for all 3 layers in one kernel ----------------
__global__ void k_bsplit_all(
    const float* __restrict__ W2_0, const float* __restrict__ b2_0, const float* __restrict__ rt_0,
    const float* __restrict__ W2_1, const float* __restrict__ b2_1, const float* __restrict__ rt_1,
    const float* __restrict__ W2_2, const float* __restrict__ b2_2, const float* __restrict__ rt_2)
{
    int idx = blockIdx.x * blockDim.x + threadIdx.x;
    if (idx >= BTOT) return;
    int rel, ci, co, K;
    const float *W2, *b2, *rt;
    if (idx < BOFF1)      { rel = idx;         ci = 16; co = 32; K = 2048; W2 = W2_0; b2 = b2_0; rt = rt_0; }
    else if (idx < BOFF2) { rel = idx - BOFF1; ci = 32; co = 64; K = 4096; W2 = W2_1; b2 = b2_1; rt = rt_1; }
    else                  { rel = idx - BOFF2; ci = 64; co = 64; K = 8192; W2 = W2_2; b2 = b2_2; rt = rt_2; }
    int kk = rel / co, o = rel % co;
    float w;
    if (kk < K) {
        int i = kk >> 7, k = kk & 127;
        w = W2[(k * ci + i) * co + o];
    } else if (kk < K + ci) {
        w = b2[(kk - K) * co + o];
    } else if (kk < K + 2 * ci) {
        w = rt[(kk - K - ci) * co + o];
    } else {
        w = 0.f;
    }
    __nv_bfloat16 h = __float2bfloat16(w);
    __nv_bfloat16 lo = __float2bfloat16(w - __bfloat162float(h));
    g_Bhi[idx] = h;
    g_Blo[idx] = lo;
}

// ---------------- scatter: S'[n] = [S | xs | x | 0pad] as bf16 hi/lo ----------------
template <int CI>
__global__ __launch_bounds__(128) void k_scatter(
    const float* __restrict__ xcur, const int* __restrict__ ei,
    const float* __restrict__ eattr, const float* __restrict__ W1,
    const float* __restrict__ b1, int KP)
{
    constexpr int K = CI * 128;
    int n = blockIdx.x;
    int t = threadIdx.x;
    int w = t >> 5, lane = t & 31;
    __shared__ float sx[4][CI];
    __shared__ float sattr[4][5];

    float w1r[5];
#pragma unroll
    for (int j = 0; j < 5; j++) w1r[j] = W1[j * HID + t];
    float b1r = b1[t];

    float sacc[CI];
#pragma unroll
    for (int i = 0; i < CI; i++) sacc[i] = 0.f;
    float xsacc = 0.f;

    int beg = g_rowptr[n], end = g_rowptr[n + 1];
    for (int j0 = beg; j0 < end; j0 += 4) {
        int cnt = min(4, end - j0);
        if (w < cnt) {
            int e = g_eperm[j0 + w];
            int src = ei[e];
            if (lane < 5) sattr[w][lane] = eattr[e * 5 + lane];
#pragma unroll
            for (int i = lane; i < CI; i += 32) sx[w][i] = xcur[src * CI + i];
        }
        __syncthreads();
        for (int c = 0; c < cnt; c++) {
            float h = b1r;
#pragma unroll
            for (int q = 0; q < 5; q++) h += sattr[c][q] * w1r[q];
            h = fmaxf(h, 0.f);
#pragma unroll
            for (int i = 0; i < CI; i++) sacc[i] += h * sx[c][i];
            if (t < CI) xsacc += sx[c][t];
        }
        __syncthreads();
    }

    size_t base = (size_t)n * KP;
#pragma unroll
    for (int i = 0; i < CI; i++) {
        float v = sacc[i];
        __nv_bfloat16 h = __float2bfloat16(v);
        __nv_bfloat16 lo = __float2bfloat16(v - __bfloat162float(h));
        g_Shi[base + (size_t)i * HID + t] = h;
        g_Slo[base + (size_t)i * HID + t] = lo;
    }
    int ext = KP - K;
    if (t < ext) {
        float v;
        if (t < CI) v = xsacc;
        else if (t < 2 * CI) v = xcur[n * CI + (t - CI)];
        else v = 0.f;
        __nv_bfloat16 h = __float2bfloat16(v);
        __nv_bfloat16 lo = __float2bfloat16(v - __bfloat162float(h));
        g_Shi[base + K + t] = h;
        g_Slo[base + K + t] = lo;
    }
}

// ---------------- fused GEMM + epilogue ----------------
// xnext[M, CO] = elu( S'[M, K'] @ B'[K', CO] + bias )
// BM=64, BK=64, 8 warps; 4-stage cp.async ring (wait_group 2, 1 sync/iter);
// bf16 hi/lo 3-product HMMA.
template <int CO>
__global__ __launch_bounds__(256) void k_gemm_mma(int KP, int boff,
                                                  float* __restrict__ xnext,
                                                  const float* __restrict__ bias)
{
    constexpr int AP = 72;                 // padded A row (bf16 elems)
    constexpr int BP = CO + 8;             // padded B row
    constexpr int WNR = CO / 2;
    constexpr int NT = WNR / 8;
    constexpr int NPAIR = NT / 2;
    constexpr uint32_t AH_OFF = 0;
    constexpr uint32_t AL_OFF = 64 * AP * 2;               // 9216
    constexpr uint32_t BH_OFF = AL_OFF * 2;                // 18432
    constexpr uint32_t BL_OFF = BH_OFF + 64 * BP * 2;
    constexpr uint32_t STAGE = BL_OFF + 64 * BP * 2;
    constexpr int NSTAGE = 4;

    extern __shared__ char smem[];
    const uint32_t sb = smem_u32(smem);

    const int t = threadIdx.x;
    const int wid = t >> 5, lane = t & 31;
    const int wm = wid & 3;
    const int wn = wid >> 2;
    const int m0 = blockIdx.x * 64;

    float acc[NT][4];
#pragma unroll
    for (int i = 0; i < NT; i++)
#pragma unroll
        for (int j = 0; j < 4; j++) acc[i][j] = 0.f;

    const int nIter = KP / 64;

    auto issue = [&](int sg, int kt) {
        uint32_t s0 = sb + sg * STAGE;
#pragma unroll
        for (int p = 0; p < 2; p++) {
            int c = t + 256 * p;
            int row = c >> 3, cc = c & 7;
            uint32_t d = s0 + (uint32_t)(row * AP + cc * 8) * 2u;
            const __nv_bfloat16* sh = &g_Shi[(size_t)(m0 + row) * KP + kt + cc * 8];
            const __nv_bfloat16* sl = &g_Slo[(size_t)(m0 + row) * KP + kt + cc * 8];
            CP_ASYNC16(d + AH_OFF, sh);
            CP_ASYNC16(d + AL_OFF, sl);
        }
        if (CO == 64) {
#pragma unroll
            for (int p = 0; p < 2; p++) {
                int c = t + 256 * p;
                int row = c >> 3, cc = c & 7;
                uint32_t d = s0 + (uint32_t)(row * BP + cc * 8) * 2u;
                const __nv_bfloat16* bh = &g_Bhi[boff + (size_t)(kt + row) * CO + cc * 8];
                const __nv_bfloat16* bl = &g_Blo[boff + (size_t)(kt + row) * CO + cc * 8];
                CP_ASYNC16(d + BH_OFF, bh);
                CP_ASYNC16(d + BL_OFF, bl);
            }
        } else {
            int c = t;
            int row = c >> 2, cc = c & 3;
            uint32_t d = s0 + (uint32_t)(row * BP + cc * 8) * 2u;
            const __nv_bfloat16* bh = &g_Bhi[boff + (size_t)(kt + row) * CO + cc * 8];
            const __nv_bfloat16* bl = &g_Blo[boff + (size_t)(kt + row) * CO + cc * 8];
            CP_ASYNC16(d + BH_OFF, bh);
            CP_ASYNC16(d + BL_OFF, bl);
        }
    };

    // prologue: fill 3 stages (nIter >= 33 always)
#pragma unroll
    for (int s = 0; s < NSTAGE - 1; s++) {
        issue(s, s * 64);
        CP_COMMIT();
    }

    for (int it = 0; it < nIter; it++) {
        CP_WAIT2();              // stage `it` resident (FIFO: all but last 2 groups done)
        __syncthreads();         // all threads' stage-`it` data visible; prev compute done

        // issue stage it+3 into ring slot (it+3)%4 (reused from iter it-1)
        if (it + NSTAGE - 1 < nIter) issue((it + NSTAGE - 1) & (NSTAGE - 1),
                                           (it + NSTAGE - 1) * 64);
        CP_COMMIT();             // empty group at tail keeps FIFO accounting

        uint32_t s0 = sb + (it & (NSTAGE - 1)) * STAGE;
#pragma unroll
        for (int ks = 0; ks < 4; ks++) {
            uint32_t a_off = s0 + (uint32_t)((wm * 16 + (lane & 15)) * AP +
                                             ks * 16 + (lane >> 4) * 8) * 2u;
            uint32_t ah0, ah1, ah2, ah3, al0, al1, al2, al3;
            ldsm_x4(ah0, ah1, ah2, ah3, a_off + AH_OFF);
            ldsm_x4(al0, al1, al2, al3, a_off + AL_OFF);

#pragma unroll
            for (int p = 0; p < NPAIR; p++) {
                int nb = wn * WNR + p * 16;
                uint32_t b_off = s0 + (uint32_t)((ks * 16 + (lane & 15)) * BP +
                                                 nb + (lane >> 4) * 8) * 2u;
                uint32_t bh0, bh1, bh2, bh3, bl0, bl1, bl2, bl3;
                ldsm_x4t(bh0, bh1, bh2, bh3, b_off + BH_OFF);
                ldsm_x4t(bl0, bl1, bl2, bl3, b_off + BL_OFF);

                float* c0 = acc[p * 2 + 0];
                float* c1 = acc[p * 2 + 1];
                mma_bf16(c0[0], c0[1], c0[2], c0[3], ah0, ah1, ah2, ah3, bh0, bh1);
                mma_bf16(c1[0], c1[1], c1[2], c1[3], ah0, ah1, ah2, ah3, bh2, bh3);
                mma_bf16(c0[0], c0[1], c0[2], c0[3], ah0, ah1, ah2, ah3, bl0, bl1);
                mma_bf16(c1[0], c1[1], c1[2], c1[3], ah0, ah1, ah2, ah3, bl2, bl3);
                mma_bf16(c0[0], c0[1], c0[2], c0[3], al0, al1, al2, al3, bh0, bh1);
                mma_bf16(c1[0], c1[1], c1[2], c1[3], al0, al1, al2, al3, bh2, bh3);
            }
        }
    }

    // fused epilogue: elu(acc + bias) -> xnext
    const int row0 = lane >> 2;
    const int col0 = (lane & 3) * 2;
#pragma unroll
    for (int nt = 0; nt < NT; nt++) {
        int m = m0 + wm * 16 + row0;
        int c = wn * WNR + nt * 8 + col0;
        float b0 = bias[c], b1v = bias[c + 1];
        float v0 = acc[nt][0] + b0, v1 = acc[nt][1] + b1v;
        float v2 = acc[nt][2] + b0, v3 = acc[nt][3] + b1v;
        v0 = (v0 > 0.f) ? v0 : expm1f(v0);
        v1 = (v1 > 0.f) ? v1 : expm1f(v1);
        v2 = (v2 > 0.f) ? v2 : expm1f(v2);
        v3 = (v3 > 0.f) ? v3 : expm1f(v3);
        *(float2*)&xnext[(size_t)m * CO + c] = make_float2(v0, v1);
        *(float2*)&xnext[(size_t)(m + 8) * CO + c] = make_float2(v2, v3);
    }
}

// ---------------- pooling ----------------
__global__ void k_pool1(const float* __restrict__ x3, const int* __restrict__ n2s) {
    int idx = blockIdx.x * blockDim.x + threadIdx.x;
    if (idx >= N_NODES * 64) return;
    int n = idx / 64, o = idx % 64;
    int s = n2s[n];
    atomicAdd(&g_sub[s * 64 + o], x3[idx]);
    if (o == 0) atomicAdd(&g_subcnt[s], 1.f);
}

__global__ void k_pool2(const int* __restrict__ s2g) {
    int idx = blockIdx.x * blockDim.x + threadIdx.x;
    if (idx >= N_SUB * 64) return;
    int s = idx / 64, o = idx % 64;
    float m = g_sub[idx] / fmaxf(g_subcnt[s], 1.f);
    int g = s2g[s];
    atomicAdd(&g_graph[g * 64 + o], m);
    if (o == 0) atomicAdd(&g_graphcnt[g], 1.f);
}

// ---------------- final MLP (single block) ----------------
__global__ void k_fc(const float* __restrict__ fc1w, const float* __restrict__ fc1b,
                     const float* __restrict__ fc2w, const float* __restrict__ fc2b,
                     const float* __restrict__ fc3w, const float* __restrict__ fc3b,
                     float* __restrict__ out)
{
    __shared__ float hg[32 * 64];
    __shared__ float h1[32 * 32];
    __shared__ float h2[32 * 16];
    int t = threadIdx.x;  // 256
    for (int idx = t; idx < 32 * 64; idx += 256) {
        int g = idx / 64;
        hg[idx] = g_graph[idx] / fmaxf(g_graphcnt[g], 1.f);
    }
    __syncthreads();
    for (int idx = t; idx < 32 * 32; idx += 256) {
        int g = idx / 32, o = idx % 32;
        float v = fc1b[o];
        for (int i = 0; i < 64; i++) v += hg[g * 64 + i] * fc1w[i * 32 + o];
        h1[idx] = (v > 0.f) ? v : expm1f(v);
    }
    __syncthreads();
    for (int idx = t; idx < 32 * 16; idx += 256) {
        int g = idx / 16, o = idx % 16;
        float v = fc2b[o];
        for (int i = 0; i < 32; i++) v += h1[g * 32 + i] * fc2w[i * 16 + o];
        h2[idx] = (v > 0.f) ? v : expm1f(v);
    }
    __syncthreads();
    if (t < 32) {
        float v = fc3b[0];
        for (int i = 0; i < 16; i++) v += h2[t * 16 + i] * fc3w[i];
        out[t] = v;
    }
}

// ---------------- host launch ----------------
extern "C" void kernel_launch(void* const* d_in, const int* in_sizes, int n_in,
                              void* d_out, int out_size)
{
    const float* x     = (const float*)d_in[0];
    const int*   ei    = (const int*)d_in[1];
    const float* eattr = (const float*)d_in[2];
    const int*   n2s   = (const int*)d_in[3];
    const int*   s2g   = (const int*)d_in[4];
    const float* W1[3]   = {(const float*)d_in[5],  (const float*)d_in[11], (const float*)d_in[17]};
    const float* b1[3]   = {(const float*)d_in[6],  (const float*)d_in[12], (const float*)d_in[18]};
    const float* W2[3]   = {(const float*)d_in[7],  (const float*)d_in[13], (const float*)d_in[19]};
    const float* b2[3]   = {(const float*)d_in[8],  (const float*)d_in[14], (const float*)d_in[20]};
    const float* root[3] = {(const float*)d_in[9],  (const float*)d_in[15], (const float*)d_in[21]};
    const float* bias[3] = {(const float*)d_in[10], (const float*)d_in[16], (const float*)d_in[22]};
    const float* fc1w = (const float*)d_in[23];
    const float* fc1b = (const float*)d_in[24];
    const float* fc2w = (const float*)d_in[25];
    const float* fc2b = (const float*)d_in[26];
    const float* fc3w = (const float*)d_in[27];
    const float* fc3b = (const float*)d_in[28];
    float* out = (float*)d_out;

    float *xa, *xb;
    cudaGetSymbolAddress((void**)&xa, g_xa);
    cudaGetSymbolAddress((void**)&xb, g_xb);

    // dynamic smem: 4 stages. CO=64: 4*36864=147456B; CO=32: 4*28672=114688B
    static bool attr_set = false;
    if (!attr_set) {
        cudaFuncSetAttribute(k_gemm_mma<64>, cudaFuncAttributeMaxDynamicSharedMemorySize, 147456);
        cudaFuncSetAttribute(k_gemm_mma<32>, cudaFuncAttributeMaxDynamicSharedMemorySize, 114688);
        attr_set = true;
    }

    // CSR by dst + pool zeroing (grid covers N_SUB*64)
    k_init<<<(N_SUB * 64 + 255) / 256, 256>>>();
    k_count<<<N_EDGES / 256, 256>>>(ei);
    k_scan<<<1, 1024>>>();
    k_fill<<<N_EDGES / 256, 256>>>(ei);
    k_bsplit_all<<<(BTOT + 255) / 256, 256>>>(W2[0], b2[0], root[0],
                                              W2[1], b2[1], root[1],
                                              W2[2], b2[2], root[2]);

    const int KP[3] = {KP0, KP1, KP2};
    const int BOFF[3] = {BOFF0, BOFF1, BOFF2};
    const float* xcur = x;
    float* xnext = xa;

    for (int l = 0; l < 3; l++) {
        if (l == 0)      k_scatter<16><<<N_NODES, 128>>>(xcur, ei, eattr, W1[l], b1[l], KP[l]);
        else if (l == 1) k_scatter<32><<<N_NODES, 128>>>(xcur, ei, eattr, W1[l], b1[l], KP[l]);
        else             k_scatter<64><<<N_NODES, 128>>>(xcur, ei, eattr, W1[l], b1[l], KP[l]);

        if (l == 0)
            k_gemm_mma<32><<<N_NODES / 64, 256, 114688>>>(KP[l], BOFF[l], xnext, bias[l]);
        else
            k_gemm_mma<64><<<N_NODES / 64, 256, 147456>>>(KP[l], BOFF[l], xnext, bias[l]);

        xcur = xnext;
        xnext = (xnext == xa) ? xb : xa;
    }

    // pooling + MLP head
    k_pool1<<<(N_NODES * 64 + 255) / 256, 256>>>(xcur, n2s);
    k_pool2<<<(N_SUB * 64 + 255) / 256, 256>>>(s2g);
    k_fc<<<1, 256>>>(fc1w, fc1b, fc2w, fc2b, fc3w, fc3b, out);
}